// round 10
// baseline (speedup 1.0000x reference)
#include <cuda_runtime.h>
#include <cuda_bf16.h>
#include <cstdint>

// ============================================================================
// Problem constants
// ============================================================================
#define NROWS 16384
#define MCOLS 16384
#define DDIM  512

#define BLOCK_M 128                 // X rows per CTA
#define TILE_N  128                 // Y rows per M-tile
#define NTILES  (MCOLS / TILE_N)    // 128
#define KCHUNK  64                  // K elems per B chunk
#define NUM_KC  (DDIM / KCHUNK)     // 8
#define NITER   (NTILES * NUM_KC)   // 1024 chunks
#define STAGES  4                   // per-pair pipeline depth
#define NTHREADS 256                // 8 warps: 2 (M) x 4 (N), warp tile 64x32

// SMEM layout (bytes). A padded to stride 520 bf16.
// B: per-warpN-PAIR shared slices: 32 rows x 64 K bf16, row stride 144 B,
//    4 stages deep. 4 warpN groups x 4 stages x 4608 B = 73728 B.
#define SA 520
#define SBW_BYTES   144                         // 128 B data + 16 pad
#define SLICE_BYTES (32 * SBW_BYTES)            // 4608
#define A_BYTES     (BLOCK_M * SA * 2)          // 133120
#define SM_A    0
#define SM_B    (A_BYTES)
#define SM_X2   (SM_B + 4 * STAGES * SLICE_BYTES)  // 206848: x2 per row (128 f32)
#define SM_RMIN (SM_X2 + 512)                   // row mins (128 f32)
#define SM_RED  (SM_RMIN + 512)                 // 8 f32
#define SM_FLAG (SM_RED + 64)                   // last-CTA flag
#define SMEM_TOTAL (SM_FLAG + 16)               // ~208 KB

// ============================================================================
// Device globals (no allocations allowed)
// ============================================================================
__device__ __nv_bfloat16 g_ybf[(size_t)MCOLS * DDIM];
__device__ float g_c[MCOLS];
__device__ float g_psipart[MCOLS / 8];        // 2048 prep-block psi partials
__device__ float g_accpart[NROWS / BLOCK_M];  // 128 per-CTA row-sum partials
__device__ unsigned int g_done;               // ticket; reset by last CTA

// ============================================================================
// PTX helpers (sm_80-safe only: cp.async, ldmatrix, mma.sync, named bar)
// ============================================================================
__device__ __forceinline__ uint32_t smem_to_u32(const void* p) {
    uint32_t a;
    asm("{ .reg .u64 t; cvta.to.shared.u64 t, %1; cvt.u32.u64 %0, t; }" : "=r"(a) : "l"(p));
    return a;
}

__device__ __forceinline__ void cp16(uint32_t dst, const void* src) {
    asm volatile("cp.async.cg.shared.global [%0], [%1], 16;" :: "r"(dst), "l"(src) : "memory");
}
#define CP_COMMIT() asm volatile("cp.async.commit_group;" ::: "memory")
#define CP_WAIT(n)  asm volatile("cp.async.wait_group %0;" :: "n"(n) : "memory")

#define PAIR_BAR(id) asm volatile("bar.sync %0, 64;" :: "r"(id) : "memory")

#define LDMX4(r0, r1, r2, r3, addr) \
    asm volatile("ldmatrix.sync.aligned.m8n8.x4.shared.b16 {%0,%1,%2,%3}, [%4];" \
        : "=r"(r0), "=r"(r1), "=r"(r2), "=r"(r3) : "r"(addr))

#define MMA16816(d0, d1, d2, d3, a0, a1, a2, a3, b0, b1) \
    asm volatile("mma.sync.aligned.m16n8k16.row.col.f32.bf16.bf16.f32 " \
        "{%0,%1,%2,%3}, {%4,%5,%6,%7}, {%8,%9}, {%0,%1,%2,%3};" \
        : "+f"(d0), "+f"(d1), "+f"(d2), "+f"(d3) \
        : "r"(a0), "r"(a1), "r"(a2), "r"(a3), "r"(b0), "r"(b1))

__device__ __forceinline__ uint32_t pack_bf16x2(float lo, float hi) {
    uint32_t u;
    asm("cvt.rn.bf16x2.f32 %0, %1, %2;" : "=r"(u) : "f"(hi), "f"(lo));
    return u;
}

// ============================================================================
// Kernel: prep — Y -> bf16, c[m] = ||y_m||^2 - psi[m], per-block psi partials
// ============================================================================
__global__ void prep_kernel(const float* __restrict__ y, const float* __restrict__ psi) {
    __shared__ float spsi[8];
    int wid = threadIdx.x >> 5, lane = threadIdx.x & 31;
    int row = blockIdx.x * 8 + wid;
    const float4* yr = (const float4*)(y + (size_t)row * DDIM);
    uint32_t* yb = ((uint32_t*)g_ybf) + (size_t)row * (DDIM / 2);
    float s = 0.f;
#pragma unroll
    for (int i = 0; i < 4; i++) {
        int idx = i * 32 + lane;
        float4 v = yr[idx];
        s += v.x * v.x + v.y * v.y + v.z * v.z + v.w * v.w;
        yb[idx * 2]     = pack_bf16x2(v.x, v.y);
        yb[idx * 2 + 1] = pack_bf16x2(v.z, v.w);
    }
#pragma unroll
    for (int o = 16; o; o >>= 1) s += __shfl_xor_sync(0xffffffffu, s, o);
    if (lane == 0) {
        float p = psi[row];
        g_c[row] = s - p;
        spsi[wid] = p;
    }
    __syncthreads();
    if (threadIdx.x == 0) {
        float ps = 0.f;
#pragma unroll
        for (int i = 0; i < 8; i++) ps += spsi[i];
        g_psipart[blockIdx.x] = ps;
    }
}

// ============================================================================
// Pair-shared B chunk issue: warpM halves split the 32-row slice (16 rows
// each = 128 x 16B transfers, 4 per lane). Strength-reduced addressing.
// ============================================================================
__device__ __forceinline__ void issue_pair_chunk(
    uint32_t sb, int warpN, int warpM, int i, int lane
) {
    int t = i >> 3, kc = i & 7, stg = i & (STAGES - 1);
    const char* src = (const char*)g_ybf +
        ((size_t)(t * TILE_N + warpN * 32 + warpM * 16 + (lane >> 3)) * DDIM
         + (size_t)kc * KCHUNK) * 2 + (lane & 7) * 16;
    uint32_t dst = sb + SM_B + (uint32_t)(warpN * STAGES + stg) * SLICE_BYTES
                   + (uint32_t)(warpM * 16 + (lane >> 3)) * SBW_BYTES + (lane & 7) * 16;
#pragma unroll
    for (int j = 0; j < 4; j++)
        cp16(dst + j * 4 * SBW_BYTES, src + (size_t)j * 4 * DDIM * 2);
}

// ============================================================================
// Main kernel: 128 CTAs x 256 threads. A (128x512 bf16) resident in SMEM.
// B slices SHARED by warpM pairs (same warpN), 4-stage cp.async pipeline,
// pairwise named barriers only — no CTA-wide sync in the main loop.
// Warp tile 64x32 (2Mx4N), register-double-buffered fragments.
// Fused (c - 2*S) row-min epilogue; c read via __ldg (L1-resident).
// ============================================================================
__global__ void __launch_bounds__(NTHREADS, 1) semidual_main(
    const float* __restrict__ x, float* __restrict__ out
) {
    extern __shared__ char smem[];
    uint32_t sb = smem_to_u32(smem);
    int tid = threadIdx.x, lane = tid & 31, wid = tid >> 5;
    int warpM = wid >> 2, warpN = wid & 3;
    int barid = 1 + warpN;

    // -------- prologue: fill pipeline with chunks 0..2 (3 groups) --------
#pragma unroll
    for (int s = 0; s < STAGES - 1; s++) {
        issue_pair_chunk(sb, warpN, warpM, s, lane);
        CP_COMMIT();
    }

    // -------- load A rows, convert to bf16 (padded), compute x2 --------
    {
        int row = tid >> 1, half = tid & 1;   // 2 threads per row
        const float4* xr = (const float4*)(x + (size_t)(blockIdx.x * BLOCK_M + row) * DDIM
                                           + (size_t)half * 256);
        uint32_t* As = (uint32_t*)(smem + SM_A) + row * (SA / 2) + half * 128;
        float s = 0.f;
#pragma unroll
        for (int i = 0; i < 64; i++) {
            float4 v = xr[i];
            s += v.x * v.x + v.y * v.y + v.z * v.z + v.w * v.w;
            As[2 * i]     = pack_bf16x2(v.x, v.y);
            As[2 * i + 1] = pack_bf16x2(v.z, v.w);
        }
        s += __shfl_xor_sync(0xffffffffu, s, 1);
        if (half == 0) ((float*)(smem + SM_X2))[row] = s;
    }
    __syncthreads();   // A visible to all

    // -------- ldmatrix base addresses (lane-dependent parts) --------
    uint32_t aBase[4];
#pragma unroll
    for (int mt = 0; mt < 4; mt++)
        aBase[mt] = sb + SM_A +
            (((warpM * 64 + mt * 16 + (lane & 15)) * SA + (lane >> 4) * 8) * 2);
    // B within slice: lane b4 -> +8 n-rows, b3 -> +8 k (16 B), b0..2 -> row
    uint32_t bOff = ((((lane >> 4) << 3) + (lane & 7)) * SBW_BYTES)
                    + (((lane >> 3) & 1) << 4);
    uint32_t bSliceBase = sb + SM_B + (uint32_t)(warpN * STAGES) * SLICE_BYTES;

    float acc[4][4][4];
    float rmin[4][2] = {{3.0e38f, 3.0e38f}, {3.0e38f, 3.0e38f},
                        {3.0e38f, 3.0e38f}, {3.0e38f, 3.0e38f}};

    // -------- main loop: pair-paced pipeline, no CTA-wide sync --------
    for (int i = 0; i < NITER; i++) {
        int kc = i & 7, stg = i & (STAGES - 1);

        // chunk i's half-group was committed 3 iterations ago; 2 newer groups
        // (i+1, i+2) may still be in flight.
        CP_WAIT(2);
        // join the pair: partner's half of chunk i is also complete, and both
        // warps have finished computing chunk i-1 (program order) -> safe to
        // overwrite stage (i+3)&3 == (i-1)&3 below.
        PAIR_BAR(barid);

        if (i + STAGES - 1 < NITER)
            issue_pair_chunk(sb, warpN, warpM, i + STAGES - 1, lane);
        CP_COMMIT();   // commit every iteration (possibly empty group)

        if (kc == 0) {
#pragma unroll
            for (int mt = 0; mt < 4; mt++)
#pragma unroll
                for (int nb = 0; nb < 4; nb++)
#pragma unroll
                    for (int k = 0; k < 4; k++) acc[mt][nb][k] = 0.f;
        }

        uint32_t bstage = bSliceBase + (uint32_t)stg * SLICE_BYTES;
        uint32_t koffA = (uint32_t)(kc * KCHUNK) * 2;

        // ---- register double-buffered fragment pipeline over 4 k-steps ----
        uint32_t af[2][4][4], bf[2][4][2];
#pragma unroll
        for (int mt = 0; mt < 4; mt++)
            LDMX4(af[0][mt][0], af[0][mt][1], af[0][mt][2], af[0][mt][3],
                  aBase[mt] + koffA);
#pragma unroll
        for (int nb2 = 0; nb2 < 2; nb2++)
            LDMX4(bf[0][2 * nb2][0], bf[0][2 * nb2][1],
                  bf[0][2 * nb2 + 1][0], bf[0][2 * nb2 + 1][1],
                  bstage + bOff + (uint32_t)(nb2 * 16 * SBW_BYTES));

#pragma unroll
        for (int kk = 0; kk < KCHUNK / 16; kk++) {   // 4 deep
            int cur = kk & 1, nxt = cur ^ 1;
            if (kk + 1 < KCHUNK / 16) {
#pragma unroll
                for (int mt = 0; mt < 4; mt++)
                    LDMX4(af[nxt][mt][0], af[nxt][mt][1], af[nxt][mt][2], af[nxt][mt][3],
                          aBase[mt] + koffA + (kk + 1) * 32);
#pragma unroll
                for (int nb2 = 0; nb2 < 2; nb2++)
                    LDMX4(bf[nxt][2 * nb2][0], bf[nxt][2 * nb2][1],
                          bf[nxt][2 * nb2 + 1][0], bf[nxt][2 * nb2 + 1][1],
                          bstage + bOff + (uint32_t)(nb2 * 16 * SBW_BYTES) + (kk + 1) * 32);
            }
#pragma unroll
            for (int mt = 0; mt < 4; mt++)
#pragma unroll
                for (int nb = 0; nb < 4; nb++)
                    MMA16816(acc[mt][nb][0], acc[mt][nb][1], acc[mt][nb][2], acc[mt][nb][3],
                             af[cur][mt][0], af[cur][mt][1], af[cur][mt][2], af[cur][mt][3],
                             bf[cur][nb][0], bf[cur][nb][1]);
        }

        if (kc == 7) {
            // epilogue: v = c - 2*S, fold into per-thread row mins.
            int t = i >> 3;
            const float2* cg = (const float2*)(g_c + t * TILE_N + warpN * 32);
#pragma unroll
            for (int nb = 0; nb < 4; nb++) {
                float2 c2 = __ldg(cg + ((nb * 8 + (lane & 3) * 2) >> 1));
#pragma unroll
                for (int mt = 0; mt < 4; mt++) {
                    rmin[mt][0] = fminf(rmin[mt][0], fmaf(-2.f, acc[mt][nb][0], c2.x));
                    rmin[mt][0] = fminf(rmin[mt][0], fmaf(-2.f, acc[mt][nb][1], c2.y));
                    rmin[mt][1] = fminf(rmin[mt][1], fmaf(-2.f, acc[mt][nb][2], c2.x));
                    rmin[mt][1] = fminf(rmin[mt][1], fmaf(-2.f, acc[mt][nb][3], c2.y));
                }
            }
        }
    }

    // -------- per-row min across warps --------
#pragma unroll
    for (int mt = 0; mt < 4; mt++)
#pragma unroll
        for (int rh = 0; rh < 2; rh++) {
            float v = rmin[mt][rh];
            v = fminf(v, __shfl_xor_sync(0xffffffffu, v, 1));
            v = fminf(v, __shfl_xor_sync(0xffffffffu, v, 2));
            rmin[mt][rh] = v;
        }

    float* rowmin = (float*)(smem + SM_RMIN);
    int r0 = warpM * 64 + (lane >> 2);
    __syncthreads();
    if (warpN == 0 && (lane & 3) == 0) {
#pragma unroll
        for (int mt = 0; mt < 4; mt++) {
            rowmin[r0 + mt * 16]     = rmin[mt][0];
            rowmin[r0 + mt * 16 + 8] = rmin[mt][1];
        }
    }
#pragma unroll
    for (int wn = 1; wn < 4; wn++) {
        __syncthreads();
        if (warpN == wn && (lane & 3) == 0) {
#pragma unroll
            for (int mt = 0; mt < 4; mt++) {
                rowmin[r0 + mt * 16]     = fminf(rowmin[r0 + mt * 16],     rmin[mt][0]);
                rowmin[r0 + mt * 16 + 8] = fminf(rowmin[r0 + mt * 16 + 8], rmin[mt][1]);
            }
        }
    }
    __syncthreads();

    // -------- CTA row-sum partial --------
    float val = 0.f;
    if (tid < 128) val = ((float*)(smem + SM_X2))[tid] + rowmin[tid];
#pragma unroll
    for (int o = 16; o; o >>= 1) val += __shfl_xor_sync(0xffffffffu, val, o);
    float* red = (float*)(smem + SM_RED);
    if (lane == 0) red[wid] = val;
    __syncthreads();
    if (tid == 0) {
        float s = 0.f;
#pragma unroll
        for (int w = 0; w < 8; w++) s += red[w];
        g_accpart[blockIdx.x] = s;
        __threadfence();
        unsigned int old = atomicAdd(&g_done, 1u);
        *(int*)(smem + SM_FLAG) = (old == (unsigned int)(gridDim.x - 1)) ? 1 : 0;
    }
    __syncthreads();

    // -------- last-done CTA: reduce all partials, write output --------
    if (*(int*)(smem + SM_FLAG)) {
        float s = 0.f;
#pragma unroll
        for (int j = 0; j < MCOLS / 8 / NTHREADS; j++)
            s += g_psipart[tid + j * NTHREADS];
        if (tid < NROWS / BLOCK_M) s += g_accpart[tid];
#pragma unroll
        for (int o = 16; o; o >>= 1) s += __shfl_xor_sync(0xffffffffu, s, o);
        if (lane == 0) red[wid] = s;
        __syncthreads();
        if (tid == 0) {
            float tot = 0.f;
#pragma unroll
            for (int w = 0; w < 8; w++) tot += red[w];
            out[0] = tot * (1.0f / 16384.0f);
            g_done = 0;   // reset for next graph replay
        }
    }
}

// ============================================================================
// Host launch — 2 launches
// ============================================================================
extern "C" void kernel_launch(void* const* d_in, const int* in_sizes, int n_in,
                              void* d_out, int out_size) {
    const float* x   = (const float*)d_in[0];
    const float* y   = (const float*)d_in[1];
    const float* psi = (const float*)d_in[2];
    float* out = (float*)d_out;
    (void)in_sizes; (void)n_in; (void)out_size;

    cudaFuncSetAttribute(semidual_main, cudaFuncAttributeMaxDynamicSharedMemorySize,
                         SMEM_TOTAL);

    prep_kernel<<<MCOLS / 8, 256>>>(y, psi);
    semidual_main<<<NROWS / BLOCK_M, NTHREADS, SMEM_TOTAL>>>(x, out);
}

// round 11
// speedup vs baseline: 1.0009x; 1.0009x over previous
#include <cuda_runtime.h>
#include <cuda_bf16.h>
#include <cstdint>

// ============================================================================
// Problem constants
// ============================================================================
#define NROWS 16384
#define MCOLS 16384
#define DDIM  512

#define BLOCK_M 128                 // X rows per CTA
#define TILE_N  128                 // Y rows per M-tile
#define NTILES  (MCOLS / TILE_N)    // 128
#define KCHUNK  64                  // K elems per B chunk
#define NUM_KC  (DDIM / KCHUNK)     // 8
#define NITER   (NTILES * NUM_KC)   // 1024 chunks
#define STAGES  4                   // per-pair pipeline depth
#define NTHREADS 256                // 8 warps: 2 (M) x 4 (N), warp tile 64x32

// SMEM layout (bytes). A padded to stride 520 bf16.
// B: per-warpN-PAIR shared slices: 32 rows x 64 K bf16, row stride 144 B,
//    4 stages deep. 4 warpN groups x 4 stages x 4608 B = 73728 B.
#define SA 520
#define SBW_BYTES   144                         // 128 B data + 16 pad
#define SLICE_BYTES (32 * SBW_BYTES)            // 4608
#define A_BYTES     (BLOCK_M * SA * 2)          // 133120
#define SM_A    0
#define SM_B    (A_BYTES)
#define SM_X2   (SM_B + 4 * STAGES * SLICE_BYTES)  // 206848: x2 per row (128 f32)
#define SM_RMIN (SM_X2 + 512)                   // row mins (128 f32)
#define SM_RED  (SM_RMIN + 512)                 // 8 f32
#define SM_FLAG (SM_RED + 64)                   // last-CTA flag
#define SMEM_TOTAL (SM_FLAG + 16)               // ~208 KB

// ============================================================================
// Device globals (no allocations allowed)
// ============================================================================
__device__ __nv_bfloat16 g_ybf[(size_t)MCOLS * DDIM];
__device__ float g_c[MCOLS];
__device__ float g_psipart[MCOLS / 8];        // 2048 prep-block psi partials
__device__ float g_accpart[NROWS / BLOCK_M];  // 128 per-CTA row-sum partials
__device__ unsigned int g_done;               // ticket; reset by last CTA

// ============================================================================
// PTX helpers (sm_80-safe only: cp.async, ldmatrix, mma.sync, named bar)
// ============================================================================
__device__ __forceinline__ uint32_t smem_to_u32(const void* p) {
    uint32_t a;
    asm("{ .reg .u64 t; cvta.to.shared.u64 t, %1; cvt.u32.u64 %0, t; }" : "=r"(a) : "l"(p));
    return a;
}

__device__ __forceinline__ void cp16(uint32_t dst, const void* src) {
    asm volatile("cp.async.cg.shared.global [%0], [%1], 16;" :: "r"(dst), "l"(src) : "memory");
}
#define CP_COMMIT() asm volatile("cp.async.commit_group;" ::: "memory")
#define CP_WAIT(n)  asm volatile("cp.async.wait_group %0;" :: "n"(n) : "memory")

#define PAIR_BAR(id) asm volatile("bar.sync %0, 64;" :: "r"(id) : "memory")

#define LDMX4(r0, r1, r2, r3, addr) \
    asm volatile("ldmatrix.sync.aligned.m8n8.x4.shared.b16 {%0,%1,%2,%3}, [%4];" \
        : "=r"(r0), "=r"(r1), "=r"(r2), "=r"(r3) : "r"(addr))

#define MMA16816(d0, d1, d2, d3, a0, a1, a2, a3, b0, b1) \
    asm volatile("mma.sync.aligned.m16n8k16.row.col.f32.bf16.bf16.f32 " \
        "{%0,%1,%2,%3}, {%4,%5,%6,%7}, {%8,%9}, {%0,%1,%2,%3};" \
        : "+f"(d0), "+f"(d1), "+f"(d2), "+f"(d3) \
        : "r"(a0), "r"(a1), "r"(a2), "r"(a3), "r"(b0), "r"(b1))

__device__ __forceinline__ uint32_t pack_bf16x2(float lo, float hi) {
    uint32_t u;
    asm("cvt.rn.bf16x2.f32 %0, %1, %2;" : "=r"(u) : "f"(hi), "f"(lo));
    return u;
}

// ============================================================================
// Kernel: prep — Y -> bf16, c[m] = ||y_m||^2 - psi[m], per-block psi partials
// ============================================================================
__global__ void prep_kernel(const float* __restrict__ y, const float* __restrict__ psi) {
    __shared__ float spsi[8];
    int wid = threadIdx.x >> 5, lane = threadIdx.x & 31;
    int row = blockIdx.x * 8 + wid;
    const float4* yr = (const float4*)(y + (size_t)row * DDIM);
    uint32_t* yb = ((uint32_t*)g_ybf) + (size_t)row * (DDIM / 2);
    float s = 0.f;
#pragma unroll
    for (int i = 0; i < 4; i++) {
        int idx = i * 32 + lane;
        float4 v = yr[idx];
        s += v.x * v.x + v.y * v.y + v.z * v.z + v.w * v.w;
        yb[idx * 2]     = pack_bf16x2(v.x, v.y);
        yb[idx * 2 + 1] = pack_bf16x2(v.z, v.w);
    }
#pragma unroll
    for (int o = 16; o; o >>= 1) s += __shfl_xor_sync(0xffffffffu, s, o);
    if (lane == 0) {
        float p = psi[row];
        g_c[row] = s - p;
        spsi[wid] = p;
    }
    __syncthreads();
    if (threadIdx.x == 0) {
        float ps = 0.f;
#pragma unroll
        for (int i = 0; i < 8; i++) ps += spsi[i];
        g_psipart[blockIdx.x] = ps;
    }
}

// ============================================================================
// Pair-shared B chunk issue: warpM halves split the 32-row slice (16 rows
// each = 128 x 16B transfers, 4 per lane). Strength-reduced addressing.
// ============================================================================
__device__ __forceinline__ void issue_pair_chunk(
    uint32_t sb, int warpN, int warpM, int i, int lane
) {
    int t = i >> 3, kc = i & 7, stg = i & (STAGES - 1);
    const char* src = (const char*)g_ybf +
        ((size_t)(t * TILE_N + warpN * 32 + warpM * 16 + (lane >> 3)) * DDIM
         + (size_t)kc * KCHUNK) * 2 + (lane & 7) * 16;
    uint32_t dst = sb + SM_B + (uint32_t)(warpN * STAGES + stg) * SLICE_BYTES
                   + (uint32_t)(warpM * 16 + (lane >> 3)) * SBW_BYTES + (lane & 7) * 16;
#pragma unroll
    for (int j = 0; j < 4; j++)
        cp16(dst + j * 4 * SBW_BYTES, src + (size_t)j * 4 * DDIM * 2);
}

// ============================================================================
// Main kernel: 128 CTAs x 256 threads. A (128x512 bf16) resident in SMEM.
// B slices SHARED by warpM pairs (same warpN), 4-stage cp.async pipeline,
// pairwise named barriers only — no CTA-wide sync in the main loop.
// Warp tile 64x32 (2Mx4N), register-double-buffered fragments.
// Fused (c - 2*S) row-min epilogue; c read via __ldg (L1-resident).
// ============================================================================
__global__ void __launch_bounds__(NTHREADS, 1) semidual_main(
    const float* __restrict__ x, float* __restrict__ out
) {
    extern __shared__ char smem[];
    uint32_t sb = smem_to_u32(smem);
    int tid = threadIdx.x, lane = tid & 31, wid = tid >> 5;
    int warpM = wid >> 2, warpN = wid & 3;
    int barid = 1 + warpN;

    // -------- prologue: fill pipeline with chunks 0..2 (3 groups) --------
#pragma unroll
    for (int s = 0; s < STAGES - 1; s++) {
        issue_pair_chunk(sb, warpN, warpM, s, lane);
        CP_COMMIT();
    }

    // -------- load A rows, convert to bf16 (padded), compute x2 --------
    {
        int row = tid >> 1, half = tid & 1;   // 2 threads per row
        const float4* xr = (const float4*)(x + (size_t)(blockIdx.x * BLOCK_M + row) * DDIM
                                           + (size_t)half * 256);
        uint32_t* As = (uint32_t*)(smem + SM_A) + row * (SA / 2) + half * 128;
        float s = 0.f;
#pragma unroll
        for (int i = 0; i < 64; i++) {
            float4 v = xr[i];
            s += v.x * v.x + v.y * v.y + v.z * v.z + v.w * v.w;
            As[2 * i]     = pack_bf16x2(v.x, v.y);
            As[2 * i + 1] = pack_bf16x2(v.z, v.w);
        }
        s += __shfl_xor_sync(0xffffffffu, s, 1);
        if (half == 0) ((float*)(smem + SM_X2))[row] = s;
    }
    __syncthreads();   // A visible to all

    // -------- ldmatrix base addresses (lane-dependent parts) --------
    uint32_t aBase[4];
#pragma unroll
    for (int mt = 0; mt < 4; mt++)
        aBase[mt] = sb + SM_A +
            (((warpM * 64 + mt * 16 + (lane & 15)) * SA + (lane >> 4) * 8) * 2);
    // B within slice: lane b4 -> +8 n-rows, b3 -> +8 k (16 B), b0..2 -> row
    uint32_t bOff = ((((lane >> 4) << 3) + (lane & 7)) * SBW_BYTES)
                    + (((lane >> 3) & 1) << 4);
    uint32_t bSliceBase = sb + SM_B + (uint32_t)(warpN * STAGES) * SLICE_BYTES;

    float acc[4][4][4];
    float rmin[4][2] = {{3.0e38f, 3.0e38f}, {3.0e38f, 3.0e38f},
                        {3.0e38f, 3.0e38f}, {3.0e38f, 3.0e38f}};

    // -------- main loop: pair-paced pipeline, no CTA-wide sync --------
    for (int i = 0; i < NITER; i++) {
        int kc = i & 7, stg = i & (STAGES - 1);

        // chunk i's half-group was committed 3 iterations ago; 2 newer groups
        // (i+1, i+2) may still be in flight.
        CP_WAIT(2);
        // join the pair: partner's half of chunk i is also complete, and both
        // warps have finished computing chunk i-1 (program order) -> safe to
        // overwrite stage (i+3)&3 == (i-1)&3 below.
        PAIR_BAR(barid);

        if (i + STAGES - 1 < NITER)
            issue_pair_chunk(sb, warpN, warpM, i + STAGES - 1, lane);
        CP_COMMIT();   // commit every iteration (possibly empty group)

        if (kc == 0) {
#pragma unroll
            for (int mt = 0; mt < 4; mt++)
#pragma unroll
                for (int nb = 0; nb < 4; nb++)
#pragma unroll
                    for (int k = 0; k < 4; k++) acc[mt][nb][k] = 0.f;
        }

        uint32_t bstage = bSliceBase + (uint32_t)stg * SLICE_BYTES;
        uint32_t koffA = (uint32_t)(kc * KCHUNK) * 2;

        // ---- register double-buffered fragment pipeline over 4 k-steps ----
        uint32_t af[2][4][4], bf[2][4][2];
#pragma unroll
        for (int mt = 0; mt < 4; mt++)
            LDMX4(af[0][mt][0], af[0][mt][1], af[0][mt][2], af[0][mt][3],
                  aBase[mt] + koffA);
#pragma unroll
        for (int nb2 = 0; nb2 < 2; nb2++)
            LDMX4(bf[0][2 * nb2][0], bf[0][2 * nb2][1],
                  bf[0][2 * nb2 + 1][0], bf[0][2 * nb2 + 1][1],
                  bstage + bOff + (uint32_t)(nb2 * 16 * SBW_BYTES));

#pragma unroll
        for (int kk = 0; kk < KCHUNK / 16; kk++) {   // 4 deep
            int cur = kk & 1, nxt = cur ^ 1;
            if (kk + 1 < KCHUNK / 16) {
#pragma unroll
                for (int mt = 0; mt < 4; mt++)
                    LDMX4(af[nxt][mt][0], af[nxt][mt][1], af[nxt][mt][2], af[nxt][mt][3],
                          aBase[mt] + koffA + (kk + 1) * 32);
#pragma unroll
                for (int nb2 = 0; nb2 < 2; nb2++)
                    LDMX4(bf[nxt][2 * nb2][0], bf[nxt][2 * nb2][1],
                          bf[nxt][2 * nb2 + 1][0], bf[nxt][2 * nb2 + 1][1],
                          bstage + bOff + (uint32_t)(nb2 * 16 * SBW_BYTES) + (kk + 1) * 32);
            }
#pragma unroll
            for (int mt = 0; mt < 4; mt++)
#pragma unroll
                for (int nb = 0; nb < 4; nb++)
                    MMA16816(acc[mt][nb][0], acc[mt][nb][1], acc[mt][nb][2], acc[mt][nb][3],
                             af[cur][mt][0], af[cur][mt][1], af[cur][mt][2], af[cur][mt][3],
                             bf[cur][nb][0], bf[cur][nb][1]);
        }

        if (kc == 7) {
            // epilogue: v = c - 2*S, fold into per-thread row mins.
            int t = i >> 3;
            const float2* cg = (const float2*)(g_c + t * TILE_N + warpN * 32);
#pragma unroll
            for (int nb = 0; nb < 4; nb++) {
                float2 c2 = __ldg(cg + ((nb * 8 + (lane & 3) * 2) >> 1));
#pragma unroll
                for (int mt = 0; mt < 4; mt++) {
                    rmin[mt][0] = fminf(rmin[mt][0], fmaf(-2.f, acc[mt][nb][0], c2.x));
                    rmin[mt][0] = fminf(rmin[mt][0], fmaf(-2.f, acc[mt][nb][1], c2.y));
                    rmin[mt][1] = fminf(rmin[mt][1], fmaf(-2.f, acc[mt][nb][2], c2.x));
                    rmin[mt][1] = fminf(rmin[mt][1], fmaf(-2.f, acc[mt][nb][3], c2.y));
                }
            }
        }
    }

    // -------- per-row min across warps --------
#pragma unroll
    for (int mt = 0; mt < 4; mt++)
#pragma unroll
        for (int rh = 0; rh < 2; rh++) {
            float v = rmin[mt][rh];
            v = fminf(v, __shfl_xor_sync(0xffffffffu, v, 1));
            v = fminf(v, __shfl_xor_sync(0xffffffffu, v, 2));
            rmin[mt][rh] = v;
        }

    float* rowmin = (float*)(smem + SM_RMIN);
    int r0 = warpM * 64 + (lane >> 2);
    __syncthreads();
    if (warpN == 0 && (lane & 3) == 0) {
#pragma unroll
        for (int mt = 0; mt < 4; mt++) {
            rowmin[r0 + mt * 16]     = rmin[mt][0];
            rowmin[r0 + mt * 16 + 8] = rmin[mt][1];
        }
    }
#pragma unroll
    for (int wn = 1; wn < 4; wn++) {
        __syncthreads();
        if (warpN == wn && (lane & 3) == 0) {
#pragma unroll
            for (int mt = 0; mt < 4; mt++) {
                rowmin[r0 + mt * 16]     = fminf(rowmin[r0 + mt * 16],     rmin[mt][0]);
                rowmin[r0 + mt * 16 + 8] = fminf(rowmin[r0 + mt * 16 + 8], rmin[mt][1]);
            }
        }
    }
    __syncthreads();

    // -------- CTA row-sum partial --------
    float val = 0.f;
    if (tid < 128) val = ((float*)(smem + SM_X2))[tid] + rowmin[tid];
#pragma unroll
    for (int o = 16; o; o >>= 1) val += __shfl_xor_sync(0xffffffffu, val, o);
    float* red = (float*)(smem + SM_RED);
    if (lane == 0) red[wid] = val;
    __syncthreads();
    if (tid == 0) {
        float s = 0.f;
#pragma unroll
        for (int w = 0; w < 8; w++) s += red[w];
        g_accpart[blockIdx.x] = s;
        __threadfence();
        unsigned int old = atomicAdd(&g_done, 1u);
        *(int*)(smem + SM_FLAG) = (old == (unsigned int)(gridDim.x - 1)) ? 1 : 0;
    }
    __syncthreads();

    // -------- last-done CTA: reduce all partials, write output --------
    if (*(int*)(smem + SM_FLAG)) {
        float s = 0.f;
#pragma unroll
        for (int j = 0; j < MCOLS / 8 / NTHREADS; j++)
            s += g_psipart[tid + j * NTHREADS];
        if (tid < NROWS / BLOCK_M) s += g_accpart[tid];
#pragma unroll
        for (int o = 16; o; o >>= 1) s += __shfl_xor_sync(0xffffffffu, s, o);
        if (lane == 0) red[wid] = s;
        __syncthreads();
        if (tid == 0) {
            float tot = 0.f;
#pragma unroll
            for (int w = 0; w < 8; w++) tot += red[w];
            out[0] = tot * (1.0f / 16384.0f);
            g_done = 0;   // reset for next graph replay
        }
    }
}

// ============================================================================
// Host launch — 2 launches
// ============================================================================
extern "C" void kernel_launch(void* const* d_in, const int* in_sizes, int n_in,
                              void* d_out, int out_size) {
    const float* x   = (const float*)d_in[0];
    const float* y   = (const float*)d_in[1];
    const float* psi = (const float*)d_in[2];
    float* out = (float*)d_out;
    (void)in_sizes; (void)n_in; (void)out_size;

    cudaFuncSetAttribute(semidual_main, cudaFuncAttributeMaxDynamicSharedMemorySize,
                         SMEM_TOTAL);

    prep_kernel<<<MCOLS / 8, 256>>>(y, psi);
    semidual_main<<<NROWS / BLOCK_M, NTHREADS, SMEM_TOTAL>>>(x, out);
}

// round 12
// speedup vs baseline: 1.0230x; 1.0220x over previous
#include <cuda_runtime.h>
#include <cuda_bf16.h>
#include <cstdint>

// ============================================================================
// Problem constants
// ============================================================================
#define NROWS 16384
#define MCOLS 16384
#define DDIM  512

#define BLOCK_M 128                 // X rows per CTA
#define TILE_N  128                 // Y rows per M-tile
#define NTILES  (MCOLS / TILE_N)    // 128
#define KCHUNK  64                  // K elems per B chunk
#define NUM_KC  (DDIM / KCHUNK)     // 8
#define NITER   (NTILES * NUM_KC)   // 1024 chunks
#define STAGES  4                   // per-pair pipeline depth
#define NTHREADS 256                // 8 warps: 2 (M) x 4 (N), warp tile 64x32
// Warp mapping: warpM = wid&1, warpN = wid>>1  ==> a slice-sharing pair
// {2n, 2n+1} lives on DIFFERENT SMSPs (SMSP = wid&3), while the two warps
// co-resident on one SMSP (wid, wid+4) are in different pairs and stay
// decoupled. (R10 regression: pairing {n, n+4} coupled same-SMSP warps.)

// SMEM layout (bytes). A padded to stride 520 bf16.
// B: per-pair shared slices: 32 rows x 64 K bf16, row stride 144 B, 4 stages.
#define SA 520
#define SBW_BYTES   144                         // 128 B data + 16 pad
#define SLICE_BYTES (32 * SBW_BYTES)            // 4608
#define A_BYTES     (BLOCK_M * SA * 2)          // 133120
#define SM_A    0
#define SM_B    (A_BYTES)
#define SM_X2   (SM_B + 4 * STAGES * SLICE_BYTES)  // 206848: x2 per row (128 f32)
#define SM_RMIN (SM_X2 + 512)                   // row mins (128 f32)
#define SM_RED  (SM_RMIN + 512)                 // 8 f32
#define SM_FLAG (SM_RED + 64)                   // last-CTA flag
#define SMEM_TOTAL (SM_FLAG + 16)               // ~208 KB

// ============================================================================
// Device globals (no allocations allowed)
// ============================================================================
__device__ __nv_bfloat16 g_ybf[(size_t)MCOLS * DDIM];
__device__ float g_c[MCOLS];
__device__ float g_psipart[MCOLS / 8];        // 2048 prep-block psi partials
__device__ float g_accpart[NROWS / BLOCK_M];  // 128 per-CTA row-sum partials
__device__ unsigned int g_done;               // ticket; reset by last CTA

// ============================================================================
// PTX helpers (sm_80-safe only: cp.async, ldmatrix, mma.sync, named bar)
// ============================================================================
__device__ __forceinline__ uint32_t smem_to_u32(const void* p) {
    uint32_t a;
    asm("{ .reg .u64 t; cvta.to.shared.u64 t, %1; cvt.u32.u64 %0, t; }" : "=r"(a) : "l"(p));
    return a;
}

__device__ __forceinline__ void cp16(uint32_t dst, const void* src) {
    asm volatile("cp.async.cg.shared.global [%0], [%1], 16;" :: "r"(dst), "l"(src) : "memory");
}
#define CP_COMMIT() asm volatile("cp.async.commit_group;" ::: "memory")
#define CP_WAIT(n)  asm volatile("cp.async.wait_group %0;" :: "n"(n) : "memory")

#define PAIR_BAR(id) asm volatile("bar.sync %0, 64;" :: "r"(id) : "memory")

#define LDMX4(r0, r1, r2, r3, addr) \
    asm volatile("ldmatrix.sync.aligned.m8n8.x4.shared.b16 {%0,%1,%2,%3}, [%4];" \
        : "=r"(r0), "=r"(r1), "=r"(r2), "=r"(r3) : "r"(addr))

#define MMA16816(d0, d1, d2, d3, a0, a1, a2, a3, b0, b1) \
    asm volatile("mma.sync.aligned.m16n8k16.row.col.f32.bf16.bf16.f32 " \
        "{%0,%1,%2,%3}, {%4,%5,%6,%7}, {%8,%9}, {%0,%1,%2,%3};" \
        : "+f"(d0), "+f"(d1), "+f"(d2), "+f"(d3) \
        : "r"(a0), "r"(a1), "r"(a2), "r"(a3), "r"(b0), "r"(b1))

__device__ __forceinline__ uint32_t pack_bf16x2(float lo, float hi) {
    uint32_t u;
    asm("cvt.rn.bf16x2.f32 %0, %1, %2;" : "=r"(u) : "f"(hi), "f"(lo));
    return u;
}

// ============================================================================
// Kernel: prep — Y -> bf16, c[m] = ||y_m||^2 - psi[m], per-block psi partials
// ============================================================================
__global__ void prep_kernel(const float* __restrict__ y, const float* __restrict__ psi) {
    __shared__ float spsi[8];
    int wid = threadIdx.x >> 5, lane = threadIdx.x & 31;
    int row = blockIdx.x * 8 + wid;
    const float4* yr = (const float4*)(y + (size_t)row * DDIM);
    uint32_t* yb = ((uint32_t*)g_ybf) + (size_t)row * (DDIM / 2);
    float s = 0.f;
#pragma unroll
    for (int i = 0; i < 4; i++) {
        int idx = i * 32 + lane;
        float4 v = yr[idx];
        s += v.x * v.x + v.y * v.y + v.z * v.z + v.w * v.w;
        yb[idx * 2]     = pack_bf16x2(v.x, v.y);
        yb[idx * 2 + 1] = pack_bf16x2(v.z, v.w);
    }
#pragma unroll
    for (int o = 16; o; o >>= 1) s += __shfl_xor_sync(0xffffffffu, s, o);
    if (lane == 0) {
        float p = psi[row];
        g_c[row] = s - p;
        spsi[wid] = p;
    }
    __syncthreads();
    if (threadIdx.x == 0) {
        float ps = 0.f;
#pragma unroll
        for (int i = 0; i < 8; i++) ps += spsi[i];
        g_psipart[blockIdx.x] = ps;
    }
}

// ============================================================================
// Pair-shared B chunk issue: warpM halves split the 32-row slice (16 rows
// each = 128 x 16B transfers, 4 per lane). Strength-reduced addressing.
// ============================================================================
__device__ __forceinline__ void issue_pair_chunk(
    uint32_t sb, int warpN, int warpM, int i, int lane
) {
    int t = i >> 3, kc = i & 7, stg = i & (STAGES - 1);
    const char* src = (const char*)g_ybf +
        ((size_t)(t * TILE_N + warpN * 32 + warpM * 16 + (lane >> 3)) * DDIM
         + (size_t)kc * KCHUNK) * 2 + (lane & 7) * 16;
    uint32_t dst = sb + SM_B + (uint32_t)(warpN * STAGES + stg) * SLICE_BYTES
                   + (uint32_t)(warpM * 16 + (lane >> 3)) * SBW_BYTES + (lane & 7) * 16;
#pragma unroll
    for (int j = 0; j < 4; j++)
        cp16(dst + j * 4 * SBW_BYTES, src + (size_t)j * 4 * DDIM * 2);
}

// ============================================================================
// Main kernel: 128 CTAs x 256 threads. A (128x512 bf16) resident in SMEM.
// B slices shared by CROSS-SMSP warp pairs {2n, 2n+1}, 4-stage cp.async
// pipeline, pairwise named barriers only — same-SMSP warps stay decoupled.
// Warp tile 64x32 (warpM = wid&1, warpN = wid>>1), register-double-buffered
// fragments. Fused (c - 2*S) row-min epilogue; c read via __ldg.
// ============================================================================
__global__ void __launch_bounds__(NTHREADS, 1) semidual_main(
    const float* __restrict__ x, float* __restrict__ out
) {
    extern __shared__ char smem[];
    uint32_t sb = smem_to_u32(smem);
    int tid = threadIdx.x, lane = tid & 31, wid = tid >> 5;
    int warpM = wid & 1, warpN = wid >> 1;   // pair {2n,2n+1}: SMSPs 2n&3, (2n+1)&3
    int barid = 1 + warpN;

    // -------- prologue: fill pipeline with chunks 0..2 (3 groups) --------
#pragma unroll
    for (int s = 0; s < STAGES - 1; s++) {
        issue_pair_chunk(sb, warpN, warpM, s, lane);
        CP_COMMIT();
    }

    // -------- load A rows, convert to bf16 (padded), compute x2 --------
    {
        int row = tid >> 1, half = tid & 1;   // 2 threads per row
        const float4* xr = (const float4*)(x + (size_t)(blockIdx.x * BLOCK_M + row) * DDIM
                                           + (size_t)half * 256);
        uint32_t* As = (uint32_t*)(smem + SM_A) + row * (SA / 2) + half * 128;
        float s = 0.f;
#pragma unroll
        for (int i = 0; i < 64; i++) {
            float4 v = xr[i];
            s += v.x * v.x + v.y * v.y + v.z * v.z + v.w * v.w;
            As[2 * i]     = pack_bf16x2(v.x, v.y);
            As[2 * i + 1] = pack_bf16x2(v.z, v.w);
        }
        s += __shfl_xor_sync(0xffffffffu, s, 1);
        if (half == 0) ((float*)(smem + SM_X2))[row] = s;
    }
    __syncthreads();   // A visible to all

    // -------- ldmatrix base addresses (lane-dependent parts) --------
    uint32_t aBase[4];
#pragma unroll
    for (int mt = 0; mt < 4; mt++)
        aBase[mt] = sb + SM_A +
            (((warpM * 64 + mt * 16 + (lane & 15)) * SA + (lane >> 4) * 8) * 2);
    // B within slice: lane b4 -> +8 n-rows, b3 -> +8 k (16 B), b0..2 -> row
    uint32_t bOff = ((((lane >> 4) << 3) + (lane & 7)) * SBW_BYTES)
                    + (((lane >> 3) & 1) << 4);
    uint32_t bSliceBase = sb + SM_B + (uint32_t)(warpN * STAGES) * SLICE_BYTES;

    float acc[4][4][4];
    float rmin[4][2] = {{3.0e38f, 3.0e38f}, {3.0e38f, 3.0e38f},
                        {3.0e38f, 3.0e38f}, {3.0e38f, 3.0e38f}};

    // -------- main loop: pair-paced pipeline, no CTA-wide sync --------
    for (int i = 0; i < NITER; i++) {
        int kc = i & 7, stg = i & (STAGES - 1);

        // chunk i's half-group was committed 3 iterations ago; 2 newer groups
        // (i+1, i+2) may still be in flight.
        CP_WAIT(2);
        // join the pair (cross-SMSP): partner's half of chunk i complete, and
        // both warps finished chunk i-1 -> safe to overwrite stage (i+3)&3.
        PAIR_BAR(barid);

        if (i + STAGES - 1 < NITER)
            issue_pair_chunk(sb, warpN, warpM, i + STAGES - 1, lane);
        CP_COMMIT();   // commit every iteration (possibly empty group)

        if (kc == 0) {
#pragma unroll
            for (int mt = 0; mt < 4; mt++)
#pragma unroll
                for (int nb = 0; nb < 4; nb++)
#pragma unroll
                    for (int k = 0; k < 4; k++) acc[mt][nb][k] = 0.f;
        }

        uint32_t bstage = bSliceBase + (uint32_t)stg * SLICE_BYTES;
        uint32_t koffA = (uint32_t)(kc * KCHUNK) * 2;

        // ---- register double-buffered fragment pipeline over 4 k-steps ----
        uint32_t af[2][4][4], bf[2][4][2];
#pragma unroll
        for (int mt = 0; mt < 4; mt++)
            LDMX4(af[0][mt][0], af[0][mt][1], af[0][mt][2], af[0][mt][3],
                  aBase[mt] + koffA);
#pragma unroll
        for (int nb2 = 0; nb2 < 2; nb2++)
            LDMX4(bf[0][2 * nb2][0], bf[0][2 * nb2][1],
                  bf[0][2 * nb2 + 1][0], bf[0][2 * nb2 + 1][1],
                  bstage + bOff + (uint32_t)(nb2 * 16 * SBW_BYTES));

#pragma unroll
        for (int kk = 0; kk < KCHUNK / 16; kk++) {   // 4 deep
            int cur = kk & 1, nxt = cur ^ 1;
            if (kk + 1 < KCHUNK / 16) {
#pragma unroll
                for (int mt = 0; mt < 4; mt++)
                    LDMX4(af[nxt][mt][0], af[nxt][mt][1], af[nxt][mt][2], af[nxt][mt][3],
                          aBase[mt] + koffA + (kk + 1) * 32);
#pragma unroll
                for (int nb2 = 0; nb2 < 2; nb2++)
                    LDMX4(bf[nxt][2 * nb2][0], bf[nxt][2 * nb2][1],
                          bf[nxt][2 * nb2 + 1][0], bf[nxt][2 * nb2 + 1][1],
                          bstage + bOff + (uint32_t)(nb2 * 16 * SBW_BYTES) + (kk + 1) * 32);
            }
#pragma unroll
            for (int mt = 0; mt < 4; mt++)
#pragma unroll
                for (int nb = 0; nb < 4; nb++)
                    MMA16816(acc[mt][nb][0], acc[mt][nb][1], acc[mt][nb][2], acc[mt][nb][3],
                             af[cur][mt][0], af[cur][mt][1], af[cur][mt][2], af[cur][mt][3],
                             bf[cur][nb][0], bf[cur][nb][1]);
        }

        if (kc == 7) {
            // epilogue: v = c - 2*S, fold into per-thread row mins.
            int t = i >> 3;
            const float2* cg = (const float2*)(g_c + t * TILE_N + warpN * 32);
#pragma unroll
            for (int nb = 0; nb < 4; nb++) {
                float2 c2 = __ldg(cg + ((nb * 8 + (lane & 3) * 2) >> 1));
#pragma unroll
                for (int mt = 0; mt < 4; mt++) {
                    rmin[mt][0] = fminf(rmin[mt][0], fmaf(-2.f, acc[mt][nb][0], c2.x));
                    rmin[mt][0] = fminf(rmin[mt][0], fmaf(-2.f, acc[mt][nb][1], c2.y));
                    rmin[mt][1] = fminf(rmin[mt][1], fmaf(-2.f, acc[mt][nb][2], c2.x));
                    rmin[mt][1] = fminf(rmin[mt][1], fmaf(-2.f, acc[mt][nb][3], c2.y));
                }
            }
        }
    }

    // -------- per-row min across warps --------
#pragma unroll
    for (int mt = 0; mt < 4; mt++)
#pragma unroll
        for (int rh = 0; rh < 2; rh++) {
            float v = rmin[mt][rh];
            v = fminf(v, __shfl_xor_sync(0xffffffffu, v, 1));
            v = fminf(v, __shfl_xor_sync(0xffffffffu, v, 2));
            rmin[mt][rh] = v;
        }

    float* rowmin = (float*)(smem + SM_RMIN);
    int r0 = warpM * 64 + (lane >> 2);
    __syncthreads();
    if (warpN == 0 && (lane & 3) == 0) {
#pragma unroll
        for (int mt = 0; mt < 4; mt++) {
            rowmin[r0 + mt * 16]     = rmin[mt][0];
            rowmin[r0 + mt * 16 + 8] = rmin[mt][1];
        }
    }
#pragma unroll
    for (int wn = 1; wn < 4; wn++) {
        __syncthreads();
        if (warpN == wn && (lane & 3) == 0) {
#pragma unroll
            for (int mt = 0; mt < 4; mt++) {
                rowmin[r0 + mt * 16]     = fminf(rowmin[r0 + mt * 16],     rmin[mt][0]);
                rowmin[r0 + mt * 16 + 8] = fminf(rowmin[r0 + mt * 16 + 8], rmin[mt][1]);
            }
        }
    }
    __syncthreads();

    // -------- CTA row-sum partial --------
    float val = 0.f;
    if (tid < 128) val = ((float*)(smem + SM_X2))[tid] + rowmin[tid];
#pragma unroll
    for (int o = 16; o; o >>= 1) val += __shfl_xor_sync(0xffffffffu, val, o);
    float* red = (float*)(smem + SM_RED);
    if (lane == 0) red[wid] = val;
    __syncthreads();
    if (tid == 0) {
        float s = 0.f;
#pragma unroll
        for (int w = 0; w < 8; w++) s += red[w];
        g_accpart[blockIdx.x] = s;
        __threadfence();
        unsigned int old = atomicAdd(&g_done, 1u);
        *(int*)(smem + SM_FLAG) = (old == (unsigned int)(gridDim.x - 1)) ? 1 : 0;
    }
    __syncthreads();

    // -------- last-done CTA: reduce all partials, write output --------
    if (*(int*)(smem + SM_FLAG)) {
        float s = 0.f;
#pragma unroll
        for (int j = 0; j < MCOLS / 8 / NTHREADS; j++)
            s += g_psipart[tid + j * NTHREADS];
        if (tid < NROWS / BLOCK_M) s += g_accpart[tid];
#pragma unroll
        for (int o = 16; o; o >>= 1) s += __shfl_xor_sync(0xffffffffu, s, o);
        if (lane == 0) red[wid] = s;
        __syncthreads();
        if (tid == 0) {
            float tot = 0.f;
#pragma unroll
            for (int w = 0; w < 8; w++) tot += red[w];
            out[0] = tot * (1.0f / 16384.0f);
            g_done = 0;   // reset for next graph replay
        }
    }
}

// ============================================================================
// Host launch — 2 launches
// ============================================================================
extern "C" void kernel_launch(void* const* d_in, const int* in_sizes, int n_in,
                              void* d_out, int out_size) {
    const float* x   = (const float*)d_in[0];
    const float* y   = (const float*)d_in[1];
    const float* psi = (const float*)d_in[2];
    float* out = (float*)d_out;
    (void)in_sizes; (void)n_in; (void)out_size;

    cudaFuncSetAttribute(semidual_main, cudaFuncAttributeMaxDynamicSharedMemorySize,
                         SMEM_TOTAL);

    prep_kernel<<<MCOLS / 8, 256>>>(y, psi);
    semidual_main<<<NROWS / BLOCK_M, NTHREADS, SMEM_TOTAL>>>(x, out);
}

// round 14
// speedup vs baseline: 1.0819x; 1.0576x over previous
#include <cuda_runtime.h>
#include <cuda_bf16.h>
#include <cstdint>

// ============================================================================
// Problem constants
// ============================================================================
#define NROWS 16384
#define MCOLS 16384
#define DDIM  512

#define BLOCK_M 128                 // X rows per CTA
#define TILE_N  256                 // Y rows per CTA pass (8 warpN x 32)
#define NTILES  (MCOLS / TILE_N)    // 64
#define KCHUNK  32                  // K elems per per-warp B chunk
#define NUM_KC  (DDIM / KCHUNK)     // 16
#define NITER   (NTILES * NUM_KC)   // 1024 per-warp chunks
#define NTHREADS 512                // 16 warps: warpM = wid>>3, warpN = wid&7
                                    // warp tile 64x32; 4 warps per SMSP

// SMEM layout (bytes). A padded to stride 520 bf16 (1040 B, conflict-free).
// B: PER-WARP double-buffered slices: 32 rows x 32 K bf16, row stride 80 B
//    (rows mod 128B = {0,80,32,112,64,16,96,48} -> ldmatrix conflict-free).
#define SA 520
#define SBW_BYTES   80
#define SLICE_BYTES (32 * SBW_BYTES)            // 2560
#define A_BYTES     (BLOCK_M * SA * 2)          // 133120
#define SM_A    0
#define SM_B    (A_BYTES)                       // 16 warps x 2 stages x 2560
#define SM_X2   (SM_B + 16 * 2 * SLICE_BYTES)   // 215040: x2 per row (128 f32)
#define SM_RMIN (SM_X2 + 512)                   // row mins (128 f32)
#define SM_RED  (SM_RMIN + 512)                 // 16 f32
#define SM_FLAG (SM_RED + 64)                   // last-CTA flag
#define SMEM_TOTAL (SM_FLAG + 16)               // ~216 KB

// ============================================================================
// Device globals (no allocations allowed)
// ============================================================================
__device__ __nv_bfloat16 g_ybf[(size_t)MCOLS * DDIM];
__device__ float g_c[MCOLS];
__device__ float g_psipart[MCOLS / 8];        // 2048 prep-block psi partials
__device__ float g_accpart[NROWS / BLOCK_M];  // 128 per-CTA row-sum partials
__device__ unsigned int g_done;               // ticket; reset by last CTA

// ============================================================================
// PTX helpers (sm_80-safe only: cp.async, ldmatrix, mma.sync)
// ============================================================================
__device__ __forceinline__ uint32_t smem_to_u32(const void* p) {
    uint32_t a;
    asm("{ .reg .u64 t; cvta.to.shared.u64 t, %1; cvt.u32.u64 %0, t; }" : "=r"(a) : "l"(p));
    return a;
}

__device__ __forceinline__ void cp16(uint32_t dst, const void* src) {
    asm volatile("cp.async.cg.shared.global [%0], [%1], 16;" :: "r"(dst), "l"(src) : "memory");
}
#define CP_COMMIT() asm volatile("cp.async.commit_group;" ::: "memory")
#define CP_WAIT(n)  asm volatile("cp.async.wait_group %0;" :: "n"(n) : "memory")

#define LDMX4(r0, r1, r2, r3, addr) \
    asm volatile("ldmatrix.sync.aligned.m8n8.x4.shared.b16 {%0,%1,%2,%3}, [%4];" \
        : "=r"(r0), "=r"(r1), "=r"(r2), "=r"(r3) : "r"(addr))

#define MMA16816(d0, d1, d2, d3, a0, a1, a2, a3, b0, b1) \
    asm volatile("mma.sync.aligned.m16n8k16.row.col.f32.bf16.bf16.f32 " \
        "{%0,%1,%2,%3}, {%4,%5,%6,%7}, {%8,%9}, {%0,%1,%2,%3};" \
        : "+f"(d0), "+f"(d1), "+f"(d2), "+f"(d3) \
        : "r"(a0), "r"(a1), "r"(a2), "r"(a3), "r"(b0), "r"(b1))

__device__ __forceinline__ uint32_t pack_bf16x2(float lo, float hi) {
    uint32_t u;
    asm("cvt.rn.bf16x2.f32 %0, %1, %2;" : "=r"(u) : "f"(hi), "f"(lo));
    return u;
}

// ============================================================================
// Kernel: prep — Y -> bf16, c[m] = ||y_m||^2 - psi[m], per-block psi partials
// ============================================================================
__global__ void prep_kernel(const float* __restrict__ y, const float* __restrict__ psi) {
    __shared__ float spsi[8];
    int wid = threadIdx.x >> 5, lane = threadIdx.x & 31;
    int row = blockIdx.x * 8 + wid;
    const float4* yr = (const float4*)(y + (size_t)row * DDIM);
    uint32_t* yb = ((uint32_t*)g_ybf) + (size_t)row * (DDIM / 2);
    float s = 0.f;
#pragma unroll
    for (int i = 0; i < 4; i++) {
        int idx = i * 32 + lane;
        float4 v = yr[idx];
        s += v.x * v.x + v.y * v.y + v.z * v.z + v.w * v.w;
        yb[idx * 2]     = pack_bf16x2(v.x, v.y);
        yb[idx * 2 + 1] = pack_bf16x2(v.z, v.w);
    }
#pragma unroll
    for (int o = 16; o; o >>= 1) s += __shfl_xor_sync(0xffffffffu, s, o);
    if (lane == 0) {
        float p = psi[row];
        g_c[row] = s - p;
        spsi[wid] = p;
    }
    __syncthreads();
    if (threadIdx.x == 0) {
        float ps = 0.f;
#pragma unroll
        for (int i = 0; i < 8; i++) ps += spsi[i];
        g_psipart[blockIdx.x] = ps;
    }
}

// ============================================================================
// Per-warp B chunk issue: this warp's 32 Y-rows x 32 K into its own slice.
// 128 x 16B transfers, 4 per lane. lane: row = (lane>>2)+8j, ch = lane&3.
// ============================================================================
__device__ __forceinline__ void issue_warp_chunk(
    uint32_t bwarp, int warpN, int i, int lane
) {
    int t = i >> 4, kc = i & 15, stg = i & 1;
    const char* src = (const char*)g_ybf +
        ((size_t)(t * TILE_N + warpN * 32 + (lane >> 2)) * DDIM
         + (size_t)kc * KCHUNK) * 2 + (lane & 3) * 16;
    uint32_t dst = bwarp + stg * SLICE_BYTES
                   + (uint32_t)(lane >> 2) * SBW_BYTES + (lane & 3) * 16;
#pragma unroll
    for (int j = 0; j < 4; j++)
        cp16(dst + j * 8 * SBW_BYTES, src + (size_t)j * 8 * DDIM * 2);
}

// ============================================================================
// Main kernel: 128 CTAs x 512 threads (16 warps, 4 per SMSP).
// A (128x512 bf16) resident in SMEM. Each warp streams its own B slice
// (32 rows x 32 K) through a private 2-stage cp.async pipeline — NO
// cross-warp sync in the main loop; the 4 warps per SMSP interleave to
// hide LDSM/MMA/chunk-boundary stalls. Warp tile 64x32, single-buffered
// fragments (128-reg budget). Fused (c - 2*S) row-min epilogue.
// ============================================================================
__global__ void __launch_bounds__(NTHREADS, 1) semidual_main(
    const float* __restrict__ x, float* __restrict__ out
) {
    extern __shared__ char smem[];
    uint32_t sb = smem_to_u32(smem);
    int tid = threadIdx.x, lane = tid & 31, wid = tid >> 5;
    int warpM = wid >> 3, warpN = wid & 7;
    uint32_t bwarp = sb + SM_B + (uint32_t)wid * (2 * SLICE_BYTES);

    // -------- prologue: each warp starts its first B chunk --------
    issue_warp_chunk(bwarp, warpN, 0, lane);
    CP_COMMIT();

    // -------- load A rows, convert to bf16 (padded), compute x2 --------
    {
        int row = tid >> 2, q = tid & 3;   // 4 threads per row
        const float4* xr = (const float4*)(x + (size_t)(blockIdx.x * BLOCK_M + row) * DDIM
                                           + (size_t)q * 128);
        uint32_t* As = (uint32_t*)(smem + SM_A) + row * (SA / 2) + q * 64;
        float s = 0.f;
#pragma unroll
        for (int i = 0; i < 32; i++) {
            float4 v = xr[i];
            s += v.x * v.x + v.y * v.y + v.z * v.z + v.w * v.w;
            As[2 * i]     = pack_bf16x2(v.x, v.y);
            As[2 * i + 1] = pack_bf16x2(v.z, v.w);
        }
        s += __shfl_xor_sync(0xffffffffu, s, 1);
        s += __shfl_xor_sync(0xffffffffu, s, 2);
        if (q == 0) ((float*)(smem + SM_X2))[row] = s;
    }
    __syncthreads();   // A visible to all; last CTA-wide sync before tail

    // -------- ldmatrix base addresses (lane-dependent parts) --------
    uint32_t aBase[4];
#pragma unroll
    for (int mt = 0; mt < 4; mt++)
        aBase[mt] = sb + SM_A +
            (((warpM * 64 + mt * 16 + (lane & 15)) * SA + (lane >> 4) * 8) * 2);
    // B within warp slice: lane b4 -> +8 n-rows, b3 -> +16B k, b0..2 -> row
    uint32_t bOff = ((((lane >> 4) << 3) + (lane & 7)) * SBW_BYTES)
                    + (((lane >> 3) & 1) << 4);

    float acc[4][4][4];
    float rmin[4][2] = {{3.0e38f, 3.0e38f}, {3.0e38f, 3.0e38f},
                        {3.0e38f, 3.0e38f}, {3.0e38f, 3.0e38f}};

    // -------- main loop: per-warp pipeline, NO cross-warp sync --------
    for (int i = 0; i < NITER; i++) {
        int kc = i & 15, stg = i & 1;

        // issue chunk i+1 into other stage (freed by chunk i-1, program
        // order), then wait until chunk i is resident.
        if (i + 1 < NITER) {
            issue_warp_chunk(bwarp, warpN, i + 1, lane);
            CP_COMMIT();
            CP_WAIT(1);
        } else {
            CP_WAIT(0);
        }
        __syncwarp();

        if (kc == 0) {
#pragma unroll
            for (int mt = 0; mt < 4; mt++)
#pragma unroll
                for (int nb = 0; nb < 4; nb++)
#pragma unroll
                    for (int k = 0; k < 4; k++) acc[mt][nb][k] = 0.f;
        }

        uint32_t bstage = bwarp + stg * SLICE_BYTES;
        uint32_t koffA = (uint32_t)kc * (KCHUNK * 2);

        // ---- 2 k-steps, single-buffered fragments (reg budget 128) ----
#pragma unroll
        for (int kk = 0; kk < KCHUNK / 16; kk++) {
            uint32_t af[4][4], bf[4][2];
#pragma unroll
            for (int mt = 0; mt < 4; mt++)
                LDMX4(af[mt][0], af[mt][1], af[mt][2], af[mt][3],
                      aBase[mt] + koffA + kk * 32);
#pragma unroll
            for (int nb2 = 0; nb2 < 2; nb2++)
                LDMX4(bf[2 * nb2][0], bf[2 * nb2][1],
                      bf[2 * nb2 + 1][0], bf[2 * nb2 + 1][1],
                      bstage + bOff + (uint32_t)(nb2 * 16 * SBW_BYTES) + kk * 32);
#pragma unroll
            for (int mt = 0; mt < 4; mt++)
#pragma unroll
                for (int nb = 0; nb < 4; nb++)
                    MMA16816(acc[mt][nb][0], acc[mt][nb][1], acc[mt][nb][2], acc[mt][nb][3],
                             af[mt][0], af[mt][1], af[mt][2], af[mt][3],
                             bf[nb][0], bf[nb][1]);
        }

        if (kc == 15) {
            // epilogue: v = c - 2*S, fold into per-thread row mins.
            int t = i >> 4;
            const float2* cg = (const float2*)(g_c + t * TILE_N + warpN * 32);
#pragma unroll
            for (int nb = 0; nb < 4; nb++) {
                float2 c2 = __ldg(cg + ((nb * 8 + (lane & 3) * 2) >> 1));
#pragma unroll
                for (int mt = 0; mt < 4; mt++) {
                    rmin[mt][0] = fminf(rmin[mt][0], fmaf(-2.f, acc[mt][nb][0], c2.x));
                    rmin[mt][0] = fminf(rmin[mt][0], fmaf(-2.f, acc[mt][nb][1], c2.y));
                    rmin[mt][1] = fminf(rmin[mt][1], fmaf(-2.f, acc[mt][nb][2], c2.x));
                    rmin[mt][1] = fminf(rmin[mt][1], fmaf(-2.f, acc[mt][nb][3], c2.y));
                }
            }
        }
    }

    // -------- per-row min across warps --------
    // quad reduce (lanes in a quad share the same rows, different cols)
#pragma unroll
    for (int mt = 0; mt < 4; mt++)
#pragma unroll
        for (int rh = 0; rh < 2; rh++) {
            float v = rmin[mt][rh];
            v = fminf(v, __shfl_xor_sync(0xffffffffu, v, 1));
            v = fminf(v, __shfl_xor_sync(0xffffffffu, v, 2));
            rmin[mt][rh] = v;
        }

    float* rowmin = (float*)(smem + SM_RMIN);
    int r0 = warpM * 64 + (lane >> 2);
    __syncthreads();
    if (warpN == 0 && (lane & 3) == 0) {
#pragma unroll
        for (int mt = 0; mt < 4; mt++) {
            rowmin[r0 + mt * 16]     = rmin[mt][0];
            rowmin[r0 + mt * 16 + 8] = rmin[mt][1];
        }
    }
#pragma unroll
    for (int wn = 1; wn < 8; wn++) {
        __syncthreads();
        if (warpN == wn && (lane & 3) == 0) {
#pragma unroll
            for (int mt = 0; mt < 4; mt++) {
                rowmin[r0 + mt * 16]     = fminf(rowmin[r0 + mt * 16],     rmin[mt][0]);
                rowmin[r0 + mt * 16 + 8] = fminf(rowmin[r0 + mt * 16 + 8], rmin[mt][1]);
            }
        }
    }
    __syncthreads();

    // -------- CTA row-sum partial --------
    float val = 0.f;
    if (tid < 128) val = ((float*)(smem + SM_X2))[tid] + rowmin[tid];
#pragma unroll
    for (int o = 16; o; o >>= 1) val += __shfl_xor_sync(0xffffffffu, val, o);
    float* red = (float*)(smem + SM_RED);
    if (lane == 0) red[wid] = val;
    __syncthreads();
    if (tid == 0) {
        float s = 0.f;
#pragma unroll
        for (int w = 0; w < 16; w++) s += red[w];
        g_accpart[blockIdx.x] = s;
        __threadfence();
        unsigned int old = atomicAdd(&g_done, 1u);
        *(int*)(smem + SM_FLAG) = (old == (unsigned int)(gridDim.x - 1)) ? 1 : 0;
    }
    __syncthreads();

    // -------- last-done CTA: reduce all partials, write output --------
    if (*(int*)(smem + SM_FLAG)) {
        float s = 0.f;
#pragma unroll
        for (int j = 0; j < MCOLS / 8 / NTHREADS; j++)
            s += g_psipart[tid + j * NTHREADS];
        if (tid < NROWS / BLOCK_M) s += g_accpart[tid];
#pragma unroll
        for (int o = 16; o; o >>= 1) s += __shfl_xor_sync(0xffffffffu, s, o);
        if (lane == 0) red[wid] = s;
        __syncthreads();
        if (tid == 0) {
            float tot = 0.f;
#pragma unroll
            for (int w = 0; w < 16; w++) tot += red[w];
            out[0] = tot * (1.0f / 16384.0f);
            g_done = 0;   // reset for next graph replay
        }
    }
}

// ============================================================================
// Host launch — 2 launches
// ============================================================================
extern "C" void kernel_launch(void* const* d_in, const int* in_sizes, int n_in,
                              void* d_out, int out_size) {
    const float* x   = (const float*)d_in[0];
    const float* y   = (const float*)d_in[1];
    const float* psi = (const float*)d_in[2];
    float* out = (float*)d_out;
    (void)in_sizes; (void)n_in; (void)out_size;

    cudaFuncSetAttribute(semidual_main, cudaFuncAttributeMaxDynamicSharedMemorySize,
                         SMEM_TOTAL);

    prep_kernel<<<MCOLS / 8, 256>>>(y, psi);
    semidual_main<<<NROWS / BLOCK_M, NTHREADS, SMEM_TOTAL>>>(x, out);
}